// round 12
// baseline (speedup 1.0000x reference)
#include <cuda_runtime.h>

#define BB 128
#define HH 256
#define WW 256
#define SHIFT 32
#define HW (HH*WW)      // 65536
#define CHW (3*HW)      // 196608
#define RBLKS 32        // reduce role-units per image
#define BPI 64          // transform role-units per image
#define HALF (BB/2)     // 64 images per chunk

__device__ float g_part[BB * RBLKS];

// ---- reduce role: one block sums 1/32 of one image, writes one partial ----
__device__ __forceinline__ void reduce_role(const float* __restrict__ imgs,
                                            int b, int blk)
{
    const float4* p = (const float4*)(imgs + (size_t)b * CHW);
    const int per_blk = (CHW / 4) / RBLKS;   // 1536 float4
    int base = blk * per_blk;
    float s0 = 0.f, s1 = 0.f;
    #pragma unroll
    for (int i = 0; i < 6; i += 2) {         // front-batched
        float4 va = p[base + i * 256 + threadIdx.x];
        float4 vb = p[base + (i + 1) * 256 + threadIdx.x];
        s0 += (va.x + va.y) + (va.z + va.w);
        s1 += (vb.x + vb.y) + (vb.z + vb.w);
    }
    float s = s0 + s1;
    #pragma unroll
    for (int o = 16; o; o >>= 1) s += __shfl_down_sync(0xffffffffu, s, o);
    __shared__ float ss[8];
    if ((threadIdx.x & 31) == 0) ss[threadIdx.x >> 5] = s;
    __syncthreads();
    if (threadIdx.x < 8) {
        s = ss[threadIdx.x];
        #pragma unroll
        for (int o = 4; o; o >>= 1) s += __shfl_down_sync(0xffu, s, o);
        if (threadIdx.x == 0) g_part[b * RBLKS + blk] = s;
    }
}

// ---- transform role: one float4 per thread in each of 3 planes ----
__device__ __forceinline__ void transform_role(
    const float* __restrict__ imgs,
    const float* __restrict__ br,  const float* __restrict__ sat,
    const float* __restrict__ con, const int* __restrict__ tx,
    const int* __restrict__ ty,    const int* __restrict__ cx,
    const int* __restrict__ cy,    float* __restrict__ out,
    int b, int blk)
{
    int idx4 = blk * 256 + threadIdx.x;               // float4 index in plane
    int h    = idx4 >> 6;
    int w0   = (idx4 & 63) << 2;

    // One warp sums this image's 32 partials (L2-broadcast hits).
    __shared__ float sM0;
    if (threadIdx.x < 32) {
        float s = g_part[b * RBLKS + threadIdx.x];
        #pragma unroll
        for (int o = 16; o; o >>= 1) s += __shfl_down_sync(0xffffffffu, s, o);
        if (threadIdx.x == 0) sM0 = s * (1.0f / (float)CHW);
    }
    __syncthreads();

    // out = Af*v + Bf*channel_mean + Cf on valid pixels, else 0
    float a  = sat[b] * 2.0f;
    float k  = con[b] + 0.5f;
    float Af = k * a;
    float Bf = k * (1.0f - a);
    float Cf = (1.0f - k) * sM0 + (br[b] - 0.5f);

    int txs = tx[b] - SHIFT;
    int tys = ty[b] - SHIFT;
    int cxv = cx[b], cyv = cy[b];
    int xlo = max(0, cxv - 64), xhi = min(HH - 1, cxv + 63);
    int ylo = max(0, cyv - 64), yhi = min(WW - 1, cyv + 63);

    int  sh       = h + txs;
    bool rowvalid = (sh >= 0) & (sh < HH);
    bool rowcut   = (h >= xlo) & (h <= xhi);
    int  sh_c     = min(max(sh, 0), HH - 1);

    const float* src = imgs + (size_t)b * CHW + (size_t)sh_c * WW;

    float o0[4], o1[4], o2[4];
    #pragma unroll
    for (int j = 0; j < 4; j++) {
        int  w  = w0 + j;
        int  sw = w + tys;
        bool valid = rowvalid & (sw >= 0) & (sw < WW)
                   & !(rowcut & (w >= ylo) & (w <= yhi));
        int sw_c = min(max(sw, 0), WW - 1);
        if (valid) {
            float v0 = __ldcs(src + sw_c);            // last-use reads
            float v1 = __ldcs(src + HW + sw_c);
            float v2 = __ldcs(src + 2 * HW + sw_c);
            float m  = (v0 + v1 + v2) * (1.0f / 3.0f);
            float bm = fmaf(Bf, m, Cf);
            o0[j] = fmaf(Af, v0, bm);
            o1[j] = fmaf(Af, v1, bm);
            o2[j] = fmaf(Af, v2, bm);
        } else {
            o0[j] = 0.f; o1[j] = 0.f; o2[j] = 0.f;
        }
    }

    float* dst = out + (size_t)b * CHW + (size_t)h * WW + w0;
    __stcs((float4*)(dst),          make_float4(o0[0], o0[1], o0[2], o0[3]));
    __stcs((float4*)(dst + HW),     make_float4(o1[0], o1[1], o1[2], o1[3]));
    __stcs((float4*)(dst + 2 * HW), make_float4(o2[0], o2[1], o2[2], o2[3]));
}

// Mixed kernel with PDL. Every block fires the programmatic-launch trigger at
// entry (lets the NEXT node begin placing blocks as this one drains). Reduce
// roles have no upstream dependency and run immediately; transform roles gate
// on cudaGridDependencySynchronize() — full upstream completion + visibility.
// K1 (6144 blocks) interleaves roles mod 3 (1 reduce : 2 transform) so both
// DRAM directions stay live for the whole kernel (R11 win, kept).
__global__ void __launch_bounds__(256) fused_kernel(
    const float* __restrict__ imgs,
    const float* __restrict__ br,  const float* __restrict__ sat,
    const float* __restrict__ con, const int* __restrict__ tx,
    const int* __restrict__ ty,    const int* __restrict__ cx,
    const int* __restrict__ cy,    float* __restrict__ out,
    int tbase, int rbase, int nred, int ntr)
{
    cudaTriggerProgrammaticLaunchCompletion();

    if (nred > 0 && ntr > 0) {
        int r   = blockIdx.x / 3;
        int rem = blockIdx.x % 3;
        if (rem == 0) {
            reduce_role(imgs, rbase + r / RBLKS, r % RBLKS);
        } else {
            cudaGridDependencySynchronize();
            int tix = r * 2 + (rem - 1);
            transform_role(imgs, br, sat, con, tx, ty, cx, cy, out,
                           tbase + tix / BPI, tix % BPI);
        }
    } else if (nred > 0) {
        reduce_role(imgs, rbase + blockIdx.x / RBLKS, blockIdx.x % RBLKS);
    } else {
        cudaGridDependencySynchronize();
        transform_role(imgs, br, sat, con, tx, ty, cx, cy, out,
                       tbase + blockIdx.x / BPI, blockIdx.x % BPI);
    }
}

extern "C" void kernel_launch(void* const* d_in, const int* in_sizes, int n_in,
                              void* d_out, int out_size)
{
    const float* imgs = (const float*)d_in[0];
    const float* br   = (const float*)d_in[1];
    const float* sat  = (const float*)d_in[2];
    const float* con  = (const float*)d_in[3];
    const int*   tx   = (const int*)d_in[4];
    const int*   ty   = (const int*)d_in[5];
    const int*   cx   = (const int*)d_in[6];
    const int*   cy   = (const int*)d_in[7];
    float*       out  = (float*)d_out;

    const int RB = HALF * RBLKS;   // 2048 reduce blocks per half
    const int TB = HALF * BPI;     // 4096 transform blocks per half

    cudaLaunchAttribute attr[1];
    attr[0].id = cudaLaunchAttributeProgrammaticStreamSerialization;
    attr[0].val.programmaticStreamSerializationAllowed = 1;

    // K0: reduce half 0 (plain launch; fires trigger for K1's early start)
    fused_kernel<<<RB, 256>>>(imgs, br, sat, con, tx, ty, cx, cy, out,
                              /*tbase*/0, /*rbase*/0, /*nred*/HALF, /*ntr*/0);

    // K1: reduce half 1 + transform half 0 (PDL: starts during K0 drain)
    {
        cudaLaunchConfig_t cfg = {};
        cfg.gridDim = dim3(RB + TB); cfg.blockDim = dim3(256);
        cfg.attrs = attr; cfg.numAttrs = 1;
        cudaLaunchKernelEx(&cfg, fused_kernel, imgs, br, sat, con, tx, ty, cx, cy, out,
                           0, HALF, HALF, HALF);
    }
    // K2: transform half 1 (PDL: placed during K1 drain, gridsync gates data)
    {
        cudaLaunchConfig_t cfg = {};
        cfg.gridDim = dim3(TB); cfg.blockDim = dim3(256);
        cfg.attrs = attr; cfg.numAttrs = 1;
        cudaLaunchKernelEx(&cfg, fused_kernel, imgs, br, sat, con, tx, ty, cx, cy, out,
                           HALF, 0, 0, HALF);
    }
}

// round 14
// speedup vs baseline: 1.1676x; 1.1676x over previous
#include <cuda_runtime.h>

#define BB 128
#define HH 256
#define WW 256
#define SHIFT 32
#define HW (HH*WW)      // 65536
#define CHW (3*HW)      // 196608
#define RBLKS 32        // reduce role-units per image
#define BPI 64          // transform role-units per image
#define HALF (BB/2)     // 64 images per chunk

__device__ float g_part[BB * RBLKS];

// 32-byte load (8 floats) with L2 evict-last: pins the line in L2 so the
// upcoming transform pass (next graph node) hits it instead of re-reading
// DRAM. sm_103a requires the 256-bit form for this modifier.
__device__ __forceinline__ float ldg_el_sum8(const void* p) {
    unsigned long long a, b, c, d;
    asm volatile("ld.global.nc.L2::evict_last.v4.b64 {%0,%1,%2,%3}, [%4];"
                 : "=l"(a), "=l"(b), "=l"(c), "=l"(d) : "l"(p));
    float s = 0.f;
    s += __uint_as_float((unsigned)(a)) + __uint_as_float((unsigned)(a >> 32));
    s += __uint_as_float((unsigned)(b)) + __uint_as_float((unsigned)(b >> 32));
    s += __uint_as_float((unsigned)(c)) + __uint_as_float((unsigned)(c >> 32));
    s += __uint_as_float((unsigned)(d)) + __uint_as_float((unsigned)(d >> 32));
    return s;
}

// ---- reduce role: one block sums 1/32 of one image, writes one partial ----
// 24576 bytes per block = 768 x 32B loads = 3 per thread, front-batched.
// Reads pin their lines in L2 (evict_last) for the transform that follows.
__device__ __forceinline__ void reduce_role(const float* __restrict__ imgs,
                                            int b, int blk)
{
    const char* base = (const char*)(imgs + (size_t)b * CHW)
                     + (size_t)blk * 24576 + (size_t)threadIdx.x * 32;
    float s0 = ldg_el_sum8(base);
    float s1 = ldg_el_sum8(base + 256 * 32);
    float s2 = ldg_el_sum8(base + 512 * 32);
    float s = (s0 + s1) + s2;
    #pragma unroll
    for (int o = 16; o; o >>= 1) s += __shfl_down_sync(0xffffffffu, s, o);
    __shared__ float ss[8];
    if ((threadIdx.x & 31) == 0) ss[threadIdx.x >> 5] = s;
    __syncthreads();
    if (threadIdx.x < 8) {
        s = ss[threadIdx.x];
        #pragma unroll
        for (int o = 4; o; o >>= 1) s += __shfl_down_sync(0xffu, s, o);
        if (threadIdx.x == 0) g_part[b * RBLKS + blk] = s;
    }
}

// ---- transform role: one float4 per thread in each of 3 planes ----
// Gathers use __ldcs (use-and-demote: line was pinned by reduce, dies here);
// stores use __stcs (streaming, never re-read).
__device__ __forceinline__ void transform_role(
    const float* __restrict__ imgs,
    const float* __restrict__ br,  const float* __restrict__ sat,
    const float* __restrict__ con, const int* __restrict__ tx,
    const int* __restrict__ ty,    const int* __restrict__ cx,
    const int* __restrict__ cy,    float* __restrict__ out,
    int b, int blk)
{
    int idx4 = blk * 256 + threadIdx.x;               // float4 index in plane
    int h    = idx4 >> 6;
    int w0   = (idx4 & 63) << 2;

    // One warp sums this image's 32 partials (L2-broadcast hits).
    __shared__ float sM0;
    if (threadIdx.x < 32) {
        float s = g_part[b * RBLKS + threadIdx.x];
        #pragma unroll
        for (int o = 16; o; o >>= 1) s += __shfl_down_sync(0xffffffffu, s, o);
        if (threadIdx.x == 0) sM0 = s * (1.0f / (float)CHW);
    }
    __syncthreads();

    // out = Af*v + Bf*channel_mean + Cf on valid pixels, else 0
    float a  = sat[b] * 2.0f;
    float k  = con[b] + 0.5f;
    float Af = k * a;
    float Bf = k * (1.0f - a);
    float Cf = (1.0f - k) * sM0 + (br[b] - 0.5f);

    int txs = tx[b] - SHIFT;
    int tys = ty[b] - SHIFT;
    int cxv = cx[b], cyv = cy[b];
    int xlo = max(0, cxv - 64), xhi = min(HH - 1, cxv + 63);
    int ylo = max(0, cyv - 64), yhi = min(WW - 1, cyv + 63);

    int  sh       = h + txs;
    bool rowvalid = (sh >= 0) & (sh < HH);
    bool rowcut   = (h >= xlo) & (h <= xhi);
    int  sh_c     = min(max(sh, 0), HH - 1);

    const float* src = imgs + (size_t)b * CHW + (size_t)sh_c * WW;

    float o0[4], o1[4], o2[4];
    #pragma unroll
    for (int j = 0; j < 4; j++) {
        int  w  = w0 + j;
        int  sw = w + tys;
        bool valid = rowvalid & (sw >= 0) & (sw < WW)
                   & !(rowcut & (w >= ylo) & (w <= yhi));
        int sw_c = min(max(sw, 0), WW - 1);
        if (valid) {
            float v0 = __ldcs(src + sw_c);            // use-and-demote
            float v1 = __ldcs(src + HW + sw_c);
            float v2 = __ldcs(src + 2 * HW + sw_c);
            float m  = (v0 + v1 + v2) * (1.0f / 3.0f);
            float bm = fmaf(Bf, m, Cf);
            o0[j] = fmaf(Af, v0, bm);
            o1[j] = fmaf(Af, v1, bm);
            o2[j] = fmaf(Af, v2, bm);
        } else {
            o0[j] = 0.f; o1[j] = 0.f; o2[j] = 0.f;
        }
    }

    float* dst = out + (size_t)b * CHW + (size_t)h * WW + w0;
    __stcs((float4*)(dst),          make_float4(o0[0], o0[1], o0[2], o0[3]));
    __stcs((float4*)(dst + HW),     make_float4(o1[0], o1[1], o1[2], o1[3]));
    __stcs((float4*)(dst + 2 * HW), make_float4(o2[0], o2[1], o2[2], o2[3]));
}

// Mixed kernel. K1 (6144 blocks) interleaves roles mod 3 (1 reduce :
// 2 transform) so both DRAM directions stay live for the whole kernel.
// K0/K2 are pure endcaps.
__global__ void __launch_bounds__(256) fused_kernel(
    const float* __restrict__ imgs,
    const float* __restrict__ br,  const float* __restrict__ sat,
    const float* __restrict__ con, const int* __restrict__ tx,
    const int* __restrict__ ty,    const int* __restrict__ cx,
    const int* __restrict__ cy,    float* __restrict__ out,
    int tbase, int rbase, int nred, int ntr)
{
    if (nred > 0 && ntr > 0) {
        int r   = blockIdx.x / 3;
        int rem = blockIdx.x % 3;
        if (rem == 0) {
            reduce_role(imgs, rbase + r / RBLKS, r % RBLKS);
        } else {
            int tix = r * 2 + (rem - 1);
            transform_role(imgs, br, sat, con, tx, ty, cx, cy, out,
                           tbase + tix / BPI, tix % BPI);
        }
    } else if (nred > 0) {
        reduce_role(imgs, rbase + blockIdx.x / RBLKS, blockIdx.x % RBLKS);
    } else {
        transform_role(imgs, br, sat, con, tx, ty, cx, cy, out,
                       tbase + blockIdx.x / BPI, blockIdx.x % BPI);
    }
}

extern "C" void kernel_launch(void* const* d_in, const int* in_sizes, int n_in,
                              void* d_out, int out_size)
{
    const float* imgs = (const float*)d_in[0];
    const float* br   = (const float*)d_in[1];
    const float* sat  = (const float*)d_in[2];
    const float* con  = (const float*)d_in[3];
    const int*   tx   = (const int*)d_in[4];
    const int*   ty   = (const int*)d_in[5];
    const int*   cx   = (const int*)d_in[6];
    const int*   cy   = (const int*)d_in[7];
    float*       out  = (float*)d_out;

    const int RB = HALF * RBLKS;   // 2048 reduce blocks per half
    const int TB = HALF * BPI;     // 4096 transform blocks per half

    // K0: reduce half 0 (reads pinned evict-last for K1's transforms)
    fused_kernel<<<RB, 256>>>(imgs, br, sat, con, tx, ty, cx, cy, out,
                              /*tbase*/0, /*rbase*/0, /*nred*/HALF, /*ntr*/0);
    // K1: reduce half 1 + transform half 0, roles interleaved mod 3
    fused_kernel<<<RB + TB, 256>>>(imgs, br, sat, con, tx, ty, cx, cy, out,
                              /*tbase*/0, /*rbase*/HALF, /*nred*/HALF, /*ntr*/HALF);
    // K2: transform half 1
    fused_kernel<<<TB, 256>>>(imgs, br, sat, con, tx, ty, cx, cy, out,
                              /*tbase*/HALF, /*rbase*/0, /*nred*/0, /*ntr*/HALF);
}

// round 16
// speedup vs baseline: 1.1916x; 1.0206x over previous
#include <cuda_runtime.h>

#define BB 128
#define HH 256
#define WW 256
#define SHIFT 32
#define HW (HH*WW)      // 65536
#define CHW (3*HW)      // 196608
#define RBLKS 32        // reduce role-units per image
#define BPI 64          // transform role-units per image
#define HALF (BB/2)     // 64 images per chunk

__device__ float g_part[BB * RBLKS];

// 32-byte load (8 floats) with L2 evict-last: pins the line in L2 so the
// next node's transform prefetch hits it. sm_103a needs the 256-bit form.
__device__ __forceinline__ float ldg_el_sum8(const void* p) {
    unsigned long long a, b, c, d;
    asm volatile("ld.global.nc.L2::evict_last.v4.b64 {%0,%1,%2,%3}, [%4];"
                 : "=l"(a), "=l"(b), "=l"(c), "=l"(d) : "l"(p));
    float s = 0.f;
    s += __uint_as_float((unsigned)(a)) + __uint_as_float((unsigned)(a >> 32));
    s += __uint_as_float((unsigned)(b)) + __uint_as_float((unsigned)(b >> 32));
    s += __uint_as_float((unsigned)(c)) + __uint_as_float((unsigned)(c >> 32));
    s += __uint_as_float((unsigned)(d)) + __uint_as_float((unsigned)(d >> 32));
    return s;
}

// ---- reduce role: one block sums 1/32 of one image, writes one partial ----
__device__ __forceinline__ void reduce_role(const float* __restrict__ imgs,
                                            int b, int blk)
{
    const char* base = (const char*)(imgs + (size_t)b * CHW)
                     + (size_t)blk * 24576 + (size_t)threadIdx.x * 32;
    float s0 = ldg_el_sum8(base);
    float s1 = ldg_el_sum8(base + 256 * 32);
    float s2 = ldg_el_sum8(base + 512 * 32);
    float s = (s0 + s1) + s2;
    #pragma unroll
    for (int o = 16; o; o >>= 1) s += __shfl_down_sync(0xffffffffu, s, o);
    __shared__ float ss[8];
    if ((threadIdx.x & 31) == 0) ss[threadIdx.x >> 5] = s;
    __syncthreads();
    if (threadIdx.x < 8) {
        s = ss[threadIdx.x];
        #pragma unroll
        for (int o = 4; o; o >>= 1) s += __shfl_down_sync(0xffu, s, o);
        if (threadIdx.x == 0) g_part[b * RBLKS + blk] = s;
    }
}

// ---- transform role, split around the grid dependency ----
// Phase 1 (NO upstream dependency): compute gather addresses from the input
// params and issue ALL 12 input loads into registers (clamped addresses,
// unconditional — validity masking happens at the end).
// Phase 2: cudaGridDependencySynchronize() — upstream partials now visible.
// Phase 3: per-image mean -> affine constants -> mask/select -> streaming store.
__device__ __forceinline__ void transform_role(
    const float* __restrict__ imgs,
    const float* __restrict__ br,  const float* __restrict__ sat,
    const float* __restrict__ con, const int* __restrict__ tx,
    const int* __restrict__ ty,    const int* __restrict__ cx,
    const int* __restrict__ cy,    float* __restrict__ out,
    int b, int blk)
{
    int idx4 = blk * 256 + threadIdx.x;               // float4 index in plane
    int h    = idx4 >> 6;
    int w0   = (idx4 & 63) << 2;

    int txs = tx[b] - SHIFT;
    int tys = ty[b] - SHIFT;
    int cxv = cx[b], cyv = cy[b];

    int  sh       = h + txs;
    bool rowvalid = (sh >= 0) & (sh < HH);
    int  sh_c     = min(max(sh, 0), HH - 1);

    const float* src = imgs + (size_t)b * CHW + (size_t)sh_c * WW;

    // -------- phase 1: prefetch (independent of upstream kernel) --------
    float v0[4], v1[4], v2[4];
    #pragma unroll
    for (int j = 0; j < 4; j++) {
        int sw   = w0 + j + tys;
        int sw_c = min(max(sw, 0), WW - 1);
        v0[j] = __ldcs(src + sw_c);                   // use-and-demote
        v1[j] = __ldcs(src + HW + sw_c);
        v2[j] = __ldcs(src + 2 * HW + sw_c);
    }

    // -------- phase 2: wait for upstream grid (partial sums) --------
    cudaGridDependencySynchronize();

    // -------- phase 3: mean, coefficients, mask, store --------
    __shared__ float sM0;
    if (threadIdx.x < 32) {
        float s = g_part[b * RBLKS + threadIdx.x];
        #pragma unroll
        for (int o = 16; o; o >>= 1) s += __shfl_down_sync(0xffffffffu, s, o);
        if (threadIdx.x == 0) sM0 = s * (1.0f / (float)CHW);
    }
    __syncthreads();

    float a  = sat[b] * 2.0f;
    float k  = con[b] + 0.5f;
    float Af = k * a;
    float Bf = k * (1.0f - a);
    float Cf = (1.0f - k) * sM0 + (br[b] - 0.5f);

    int xlo = max(0, cxv - 64), xhi = min(HH - 1, cxv + 63);
    int ylo = max(0, cyv - 64), yhi = min(WW - 1, cyv + 63);
    bool rowcut = (h >= xlo) & (h <= xhi);

    float o0[4], o1[4], o2[4];
    #pragma unroll
    for (int j = 0; j < 4; j++) {
        int  w  = w0 + j;
        int  sw = w + tys;
        bool valid = rowvalid & (sw >= 0) & (sw < WW)
                   & !(rowcut & (w >= ylo) & (w <= yhi));
        float m  = (v0[j] + v1[j] + v2[j]) * (1.0f / 3.0f);
        float bm = fmaf(Bf, m, Cf);
        o0[j] = valid ? fmaf(Af, v0[j], bm) : 0.f;
        o1[j] = valid ? fmaf(Af, v1[j], bm) : 0.f;
        o2[j] = valid ? fmaf(Af, v2[j], bm) : 0.f;
    }

    float* dst = out + (size_t)b * CHW + (size_t)h * WW + w0;
    __stcs((float4*)(dst),          make_float4(o0[0], o0[1], o0[2], o0[3]));
    __stcs((float4*)(dst + HW),     make_float4(o1[0], o1[1], o1[2], o1[3]));
    __stcs((float4*)(dst + 2 * HW), make_float4(o2[0], o2[1], o2[2], o2[3]));
}

// Mixed kernel. Trigger fires at entry: the DEPENDENT node may begin placing
// blocks once the LAST block here has started (i.e., during our drain).
// Early-placed dependent blocks do their prefetch loads before gridsync, so
// drain slots do useful memory work instead of spinning (fixes R12).
// K1 (6144 blocks) interleaves roles mod 3 (1 reduce : 2 transform).
__global__ void __launch_bounds__(256) fused_kernel(
    const float* __restrict__ imgs,
    const float* __restrict__ br,  const float* __restrict__ sat,
    const float* __restrict__ con, const int* __restrict__ tx,
    const int* __restrict__ ty,    const int* __restrict__ cx,
    const int* __restrict__ cy,    float* __restrict__ out,
    int tbase, int rbase, int nred, int ntr)
{
    cudaTriggerProgrammaticLaunchCompletion();

    if (nred > 0 && ntr > 0) {
        int r   = blockIdx.x / 3;
        int rem = blockIdx.x % 3;
        if (rem == 0) {
            reduce_role(imgs, rbase + r / RBLKS, r % RBLKS);
        } else {
            int tix = r * 2 + (rem - 1);
            transform_role(imgs, br, sat, con, tx, ty, cx, cy, out,
                           tbase + tix / BPI, tix % BPI);
        }
    } else if (nred > 0) {
        reduce_role(imgs, rbase + blockIdx.x / RBLKS, blockIdx.x % RBLKS);
    } else {
        transform_role(imgs, br, sat, con, tx, ty, cx, cy, out,
                       tbase + blockIdx.x / BPI, blockIdx.x % BPI);
    }
}

extern "C" void kernel_launch(void* const* d_in, const int* in_sizes, int n_in,
                              void* d_out, int out_size)
{
    const float* imgs = (const float*)d_in[0];
    const float* br   = (const float*)d_in[1];
    const float* sat  = (const float*)d_in[2];
    const float* con  = (const float*)d_in[3];
    const int*   tx   = (const int*)d_in[4];
    const int*   ty   = (const int*)d_in[5];
    const int*   cx   = (const int*)d_in[6];
    const int*   cy   = (const int*)d_in[7];
    float*       out  = (float*)d_out;

    const int RB = HALF * RBLKS;   // 2048 reduce blocks per half
    const int TB = HALF * BPI;     // 4096 transform blocks per half

    cudaLaunchAttribute attr[1];
    attr[0].id = cudaLaunchAttributeProgrammaticStreamSerialization;
    attr[0].val.programmaticStreamSerializationAllowed = 1;

    // K0: reduce half 0 (plain primary)
    fused_kernel<<<RB, 256>>>(imgs, br, sat, con, tx, ty, cx, cy, out,
                              /*tbase*/0, /*rbase*/0, /*nred*/HALF, /*ntr*/0);
    // K1: reduce half 1 + transform half 0 (PDL: placed during K0 drain;
    // transforms prefetch L2-pinned half-0 before gridsync)
    {
        cudaLaunchConfig_t cfg = {};
        cfg.gridDim = dim3(RB + TB); cfg.blockDim = dim3(256);
        cfg.attrs = attr; cfg.numAttrs = 1;
        cudaLaunchKernelEx(&cfg, fused_kernel, imgs, br, sat, con, tx, ty, cx, cy, out,
                           0, HALF, HALF, HALF);
    }
    // K2: transform half 1 (PDL: placed during K1 drain; prefetch before sync)
    {
        cudaLaunchConfig_t cfg = {};
        cfg.gridDim = dim3(TB); cfg.blockDim = dim3(256);
        cfg.attrs = attr; cfg.numAttrs = 1;
        cudaLaunchKernelEx(&cfg, fused_kernel, imgs, br, sat, con, tx, ty, cx, cy, out,
                           HALF, 0, 0, HALF);
    }
}